// round 6
// baseline (speedup 1.0000x reference)
#include <cuda_runtime.h>
#include <math.h>

// Problem constants
#define Bq 16
#define Tq 750
#define Fq 4096
#define Cq 20
#define Kq 93           // T / 8
#define F4 (Fq/4)       // 1024 float4 per row
#define NROWS (Bq*Tq)   // 12000

#define CHUNK 64        // float4 per F-chunk
#define NCH (F4/CHUNK)  // 16 chunks
#define RPB 16          // rows per block
#define TPAD 768        // padded T for transposed cas

// Output layout (concatenated in reference return order, float32)
#define OFF_SA   0L
#define OFF_SB   320L
#define OFF_FA   640L
#define OFF_FB   (OFF_FA + (long)Bq*Kq*Fq)
#define OFF_FEAT (OFF_FB + (long)Bq*Kq*Fq)
#define OFF_CS   (OFF_FEAT + (long)NROWS*Fq)

// Scratch (static device globals; no runtime allocation)
__device__ float g_cas[NROWS*Cq];
__device__ float g_casT[Bq*Cq*TPAD];
__device__ float g_mag[NROWS];
__device__ int   g_idx_act[Bq*Kq];
__device__ int   g_idx_bkg[Bq*Kq];
__device__ float g_sa[Bq*Cq];
__device__ float g_sb[Bq*Cq];

// Monotone float <-> uint order map (total order)
__device__ __forceinline__ unsigned int fmap(float f)
{
    unsigned int u = __float_as_uint(f);
    return (u & 0x80000000u) ? ~u : (u | 0x80000000u);
}
__device__ __forceinline__ float funmap(unsigned int u)
{
    return (u & 0x80000000u) ? __uint_as_float(u ^ 0x80000000u)
                             : __uint_as_float(~u);
}

__device__ __forceinline__ void bar_named(int id)
{
    asm volatile("bar.sync %0, 128;" :: "r"(id) : "memory");
}

// 128-thread k-th largest using a named barrier. 4-bit radix descent.
__device__ unsigned int kth_largest_h(const unsigned int* __restrict__ v, int n,
                                      int k, int* s_hist, int ltid, int barid)
{
    unsigned int prefix = 0;
    for (int shift = 28; shift >= 0; shift -= 4) {
        if (ltid < 16) s_hist[ltid] = 0;
        bar_named(barid);
        const unsigned int mask_hi = (shift == 28) ? 0u : (0xFFFFFFFFu << (shift + 4));
        for (int t = ltid; t < n; t += 128) {
            unsigned int x = v[t];
            if ((x & mask_hi) == prefix)
                atomicAdd(&s_hist[(x >> shift) & 15], 1);
        }
        bar_named(barid);
        int kk = k;
        int d = 15;
        for (; d > 0; d--) {
            int c = s_hist[d];
            if (kk <= c) break;
            kk -= c;
        }
        prefix |= (unsigned int)d << shift;
        k = kk;
        bar_named(barid);
    }
    return prefix;
}

// ---------------------------------------------------------------------------
// K1: fused stream kernel. Block = 256 thr = 8 warps = 16 rows.
// Per chunk: warps cooperatively build p = x*mask for 16 rows in smem (+feat
// copy + sumsq), then each warp consumes 4 rows x 10 classes (class halves
// split across warp pairs). W double-buffered via cp.async; x/mask for the
// next chunk prefetched into registers during the GEMM phase.
// Dynamic smem: psh 16KB + wsh 2x20KB = 56KB.
// ---------------------------------------------------------------------------
extern __shared__ float4 smem_dyn[];

__global__ __launch_bounds__(256, 2) void k_main(const float4* __restrict__ x4,
                                                 const float4* __restrict__ m4,
                                                 const float4* __restrict__ w4,
                                                 float* __restrict__ out)
{
    float4* psh = smem_dyn;                       // [RPB][CHUNK]
    float4* wsh0 = smem_dyn + RPB * CHUNK;        // [Cq][CHUNK]
    float4* wsh1 = wsh0 + Cq * CHUNK;

    const int tid  = threadIdx.x;
    const int wid  = tid >> 5;
    const int lane = tid & 31;
    const int rbase = blockIdx.x * RPB;

    // p-phase: warp wid loads rows 2*wid, 2*wid+1
    const int pr0 = 2 * wid;
    const int pr1 = pr0 + 1;
    const float4* __restrict__ xa = x4 + (long)(rbase + pr0) * F4;
    const float4* __restrict__ xb = x4 + (long)(rbase + pr1) * F4;
    const float4* __restrict__ ma = m4 + (long)(rbase + pr0) * F4;
    const float4* __restrict__ mb = m4 + (long)(rbase + pr1) * F4;
    float4* __restrict__ fa = reinterpret_cast<float4*>(out + OFF_FEAT) + (long)(rbase + pr0) * F4;
    float4* __restrict__ fb = reinterpret_cast<float4*>(out + OFF_FEAT) + (long)(rbase + pr1) * F4;

    // GEMM assignment: 4 local rows, 10 classes
    const int rg = (wid & 3) * 4;
    const int cb = (wid >> 2) * 10;

    float acc[4][10];
#pragma unroll
    for (int r = 0; r < 4; r++)
#pragma unroll
        for (int c = 0; c < 10; c++) acc[r][c] = 0.f;
    float sq0 = 0.f, sq1 = 0.f;

    auto stage = [&](int ch, float4* dst) {
#pragma unroll
        for (int q = 0; q < (Cq * CHUNK) / 256; q++) {   // 5 per thread
            int idx = tid + 256 * q;
            const float4* src = &w4[(idx >> 6) * F4 + ch * CHUNK + (idx & (CHUNK - 1))];
            unsigned int d = (unsigned int)__cvta_generic_to_shared(&dst[idx]);
            asm volatile("cp.async.cg.shared.global [%0], [%1], 16;" :: "r"(d), "l"(src));
        }
        asm volatile("cp.async.commit_group;");
    };

    // prefetch registers for chunk 0
    float4 xv0, xv1, xv2, xv3, mv0, mv1, mv2, mv3;
    stage(0, wsh0);
    xv0 = xa[lane]; xv1 = xa[lane + 32];
    xv2 = xb[lane]; xv3 = xb[lane + 32];
    mv0 = ma[lane]; mv1 = ma[lane + 32];
    mv2 = mb[lane]; mv3 = mb[lane + 32];
    stage(1, wsh1);

    // p_write chunk 0
    {
        fa[lane] = xv0; fa[lane + 32] = xv1;
        fb[lane] = xv2; fb[lane + 32] = xv3;
        sq0 = fmaf(xv0.x,xv0.x, fmaf(xv0.y,xv0.y, fmaf(xv0.z,xv0.z, fmaf(xv0.w,xv0.w, sq0))));
        sq0 = fmaf(xv1.x,xv1.x, fmaf(xv1.y,xv1.y, fmaf(xv1.z,xv1.z, fmaf(xv1.w,xv1.w, sq0))));
        sq1 = fmaf(xv2.x,xv2.x, fmaf(xv2.y,xv2.y, fmaf(xv2.z,xv2.z, fmaf(xv2.w,xv2.w, sq1))));
        sq1 = fmaf(xv3.x,xv3.x, fmaf(xv3.y,xv3.y, fmaf(xv3.z,xv3.z, fmaf(xv3.w,xv3.w, sq1))));
        float4 p;
        p.x = xv0.x*mv0.x; p.y = xv0.y*mv0.y; p.z = xv0.z*mv0.z; p.w = xv0.w*mv0.w;
        psh[pr0*CHUNK + lane] = p;
        p.x = xv1.x*mv1.x; p.y = xv1.y*mv1.y; p.z = xv1.z*mv1.z; p.w = xv1.w*mv1.w;
        psh[pr0*CHUNK + lane + 32] = p;
        p.x = xv2.x*mv2.x; p.y = xv2.y*mv2.y; p.z = xv2.z*mv2.z; p.w = xv2.w*mv2.w;
        psh[pr1*CHUNK + lane] = p;
        p.x = xv3.x*mv3.x; p.y = xv3.y*mv3.y; p.z = xv3.z*mv3.z; p.w = xv3.w*mv3.w;
        psh[pr1*CHUNK + lane + 32] = p;
    }

    for (int ch = 0; ch < NCH; ch++) {
        float4* wb = (ch & 1) ? wsh1 : wsh0;
        const int chn = ch + 1;
        if (chn < NCH) {                 // prefetch next chunk's x/mask
            const long o = (long)chn * CHUNK;
            xv0 = xa[o + lane]; xv1 = xa[o + lane + 32];
            xv2 = xb[o + lane]; xv3 = xb[o + lane + 32];
            mv0 = ma[o + lane]; mv1 = ma[o + lane + 32];
            mv2 = mb[o + lane]; mv3 = mb[o + lane + 32];
        }
        if (ch == NCH - 1) asm volatile("cp.async.wait_group 0;");
        else               asm volatile("cp.async.wait_group 1;");
        __syncthreads();                 // p[ch] + w[ch] visible

#pragma unroll
        for (int ii = 0; ii < CHUNK / 32; ii++) {
            const int jj = lane + 32 * ii;
            float4 p0 = psh[(rg + 0) * CHUNK + jj];
            float4 p1 = psh[(rg + 1) * CHUNK + jj];
            float4 p2 = psh[(rg + 2) * CHUNK + jj];
            float4 p3 = psh[(rg + 3) * CHUNK + jj];
#pragma unroll
            for (int c = 0; c < 10; c++) {
                float4 w = wb[(cb + c) * CHUNK + jj];
                acc[0][c] = fmaf(p0.x,w.x, fmaf(p0.y,w.y, fmaf(p0.z,w.z, fmaf(p0.w,w.w, acc[0][c]))));
                acc[1][c] = fmaf(p1.x,w.x, fmaf(p1.y,w.y, fmaf(p1.z,w.z, fmaf(p1.w,w.w, acc[1][c]))));
                acc[2][c] = fmaf(p2.x,w.x, fmaf(p2.y,w.y, fmaf(p2.z,w.z, fmaf(p2.w,w.w, acc[2][c]))));
                acc[3][c] = fmaf(p3.x,w.x, fmaf(p3.y,w.y, fmaf(p3.z,w.z, fmaf(p3.w,w.w, acc[3][c]))));
            }
        }
        __syncthreads();                 // all reads of psh / wb done

        if (ch + 2 < NCH) stage(ch + 2, wb);   // refill the buffer just read

        if (chn < NCH) {                 // p_write chunk chn from prefetched regs
            const long o = (long)chn * CHUNK;
            fa[o + lane] = xv0; fa[o + lane + 32] = xv1;
            fb[o + lane] = xv2; fb[o + lane + 32] = xv3;
            sq0 = fmaf(xv0.x,xv0.x, fmaf(xv0.y,xv0.y, fmaf(xv0.z,xv0.z, fmaf(xv0.w,xv0.w, sq0))));
            sq0 = fmaf(xv1.x,xv1.x, fmaf(xv1.y,xv1.y, fmaf(xv1.z,xv1.z, fmaf(xv1.w,xv1.w, sq0))));
            sq1 = fmaf(xv2.x,xv2.x, fmaf(xv2.y,xv2.y, fmaf(xv2.z,xv2.z, fmaf(xv2.w,xv2.w, sq1))));
            sq1 = fmaf(xv3.x,xv3.x, fmaf(xv3.y,xv3.y, fmaf(xv3.z,xv3.z, fmaf(xv3.w,xv3.w, sq1))));
            float4 p;
            p.x = xv0.x*mv0.x; p.y = xv0.y*mv0.y; p.z = xv0.z*mv0.z; p.w = xv0.w*mv0.w;
            psh[pr0*CHUNK + lane] = p;
            p.x = xv1.x*mv1.x; p.y = xv1.y*mv1.y; p.z = xv1.z*mv1.z; p.w = xv1.w*mv1.w;
            psh[pr0*CHUNK + lane + 32] = p;
            p.x = xv2.x*mv2.x; p.y = xv2.y*mv2.y; p.z = xv2.z*mv2.z; p.w = xv2.w*mv2.w;
            psh[pr1*CHUNK + lane] = p;
            p.x = xv3.x*mv3.x; p.y = xv3.y*mv3.y; p.z = xv3.z*mv3.z; p.w = xv3.w*mv3.w;
            psh[pr1*CHUNK + lane + 32] = p;
        }
    }

    // reductions
#pragma unroll
    for (int off = 16; off > 0; off >>= 1) {
        sq0 += __shfl_xor_sync(0xffffffffu, sq0, off);
        sq1 += __shfl_xor_sync(0xffffffffu, sq1, off);
#pragma unroll
        for (int r = 0; r < 4; r++)
#pragma unroll
            for (int c = 0; c < 10; c++)
                acc[r][c] += __shfl_xor_sync(0xffffffffu, acc[r][c], off);
    }

    float v0 = 0.f, v1 = 0.f, v2 = 0.f, v3 = 0.f;
#pragma unroll
    for (int c = 0; c < 10; c++) {
        if (lane == c) { v0 = acc[0][c]; v1 = acc[1][c]; v2 = acc[2][c]; v3 = acc[3][c]; }
    }
    if (lane < 10) {
        g_cas[(rbase + rg + 0) * Cq + cb + lane] = v0;
        g_cas[(rbase + rg + 1) * Cq + cb + lane] = v1;
        g_cas[(rbase + rg + 2) * Cq + cb + lane] = v2;
        g_cas[(rbase + rg + 3) * Cq + cb + lane] = v3;
    }
    if (lane == 0) {
        g_mag[rbase + pr0] = sqrtf(sq0);
        g_mag[rbase + pr1] = sqrtf(sq1);
    }
}

// ---------------------------------------------------------------------------
// K1b: per-row softmax over C=20 -> cas_softmax output; also writes the
// transposed raw cas (g_casT) for coalesced k_scores loads.
// ---------------------------------------------------------------------------
__global__ __launch_bounds__(256) void k_cas_softmax(float* __restrict__ out)
{
    const int r = blockIdx.x * 8 + (threadIdx.x >> 5);
    const int lane = threadIdx.x & 31;
    if (r >= NROWS) return;
    const int b = r / Tq;
    const int t = r - b * Tq;

    float v = (lane < Cq) ? g_cas[r * Cq + lane] : -INFINITY;
    float mv = v;
#pragma unroll
    for (int off = 16; off > 0; off >>= 1)
        mv = fmaxf(mv, __shfl_xor_sync(0xffffffffu, mv, off));
    float e = (lane < Cq) ? expf(v - mv) : 0.f;
    float s = e;
#pragma unroll
    for (int off = 16; off > 0; off >>= 1)
        s += __shfl_xor_sync(0xffffffffu, s, off);
    if (lane < Cq) {
        out[OFF_CS + (long)r * Cq + lane] = e / s;
        g_casT[(b * Cq + lane) * TPAD + t] = v;
    }
}

// ---------------------------------------------------------------------------
// K2: per-batch selection (act/bkg halves concurrent via named barriers).
// ---------------------------------------------------------------------------
__global__ __launch_bounds__(256) void k_select(const float* __restrict__ sel)
{
    const int b = blockIdx.x;
    const int tid = threadIdx.x;
    __shared__ unsigned int ua[Tq];
    __shared__ unsigned int ub[Tq];
    __shared__ float red[256];
    __shared__ int s_histA[16];
    __shared__ int s_histB[16];

    float lmax = -INFINITY;
    for (int t = tid; t < Tq; t += 256) {
        float m = g_mag[b * Tq + t];
        ua[t] = __float_as_uint(m);
        lmax = fmaxf(lmax, m);
    }
    red[tid] = lmax;
    __syncthreads();
    for (int s = 128; s > 0; s >>= 1) {
        if (tid < s) red[tid] = fmaxf(red[tid], red[tid + s]);
        __syncthreads();
    }
    const float mx = red[0];
    __syncthreads();

    for (int t = tid; t < Tq; t += 256) {
        float m = __uint_as_float(ua[t]);
        float s = sel[b * Tq + t];
        float va = m * s + 0.0f;
        float vr = (mx - m) * s + 0.0f;
        ua[t] = fmap(va);
        ub[t] = fmap(vr);
    }
    __syncthreads();

    if (tid < 128) {
        const unsigned int thA = kth_largest_h(ua, Tq, Kq, s_histA, tid, 1);
        for (int t = tid; t < Tq; t += 128) {
            unsigned int xA = ua[t];
            if (xA >= thA) {
                int r = 0;
                for (int j = 0; j < Tq; j++) {
                    unsigned int u = ua[j];
                    r += (u > xA) || (u == xA && j < t);
                }
                if (r < Kq) g_idx_act[b * Kq + r] = t;
            }
        }
    } else {
        const int lt = tid - 128;
        const unsigned int thB = kth_largest_h(ub, Tq, Kq, s_histB, lt, 2);
        for (int t = lt; t < Tq; t += 128) {
            unsigned int xB = ub[t];
            if (xB >= thB) {
                int r = 0;
                for (int j = 0; j < Tq; j++) {
                    unsigned int u = ub[j];
                    r += (u > xB) || (u == xB && j < t);
                }
                if (r < Kq) g_idx_bkg[b * Kq + r] = t;
            }
        }
    }
}

// ---------------------------------------------------------------------------
// K3: gather feat_act / feat_bkg rows from x. which: 0=act, 1=bkg.
// ---------------------------------------------------------------------------
__global__ __launch_bounds__(128) void k_gather(const float4* __restrict__ x4,
                                                float* __restrict__ out, int which)
{
    const int i = blockIdx.x;           // b*93 + k
    const int b = i / Kq;
    const int t = which ? g_idx_bkg[i] : g_idx_act[i];
    const float4* __restrict__ src = x4 + ((long)(b * Tq + t)) * F4;
    float4* __restrict__ dst =
        reinterpret_cast<float4*>(out + (which ? OFF_FB : OFF_FA)) + (long)i * F4;
#pragma unroll
    for (int j = threadIdx.x; j < F4; j += 128) dst[j] = src[j];
}

// ---------------------------------------------------------------------------
// K4: warp per (b,c), coalesced loads from g_casT. 1-bit radix descent for
// the 93rd-largest; top-93 sum via threshold; bkg mean via idx list.
// ---------------------------------------------------------------------------
#define NLOC 24   // ceil(750/32)
__global__ __launch_bounds__(256) void k_scores()
{
    const int gw = (blockIdx.x * 256 + threadIdx.x) >> 5;   // 0..319
    const int lane = threadIdx.x & 31;
    if (gw >= Bq * Cq) return;
    const int b = gw / Cq;
    const int c = gw % Cq;
    const float* __restrict__ col = &g_casT[(b * Cq + c) * TPAD];

    float lv[NLOC];
    unsigned int ul[NLOC];
#pragma unroll
    for (int i = 0; i < NLOC; i++) {
        int t = lane + 32 * i;
        if (t < Tq) {
            float v = col[t];
            lv[i] = v;
            ul[i] = fmap(v);
        } else {
            lv[i] = 0.f;
            ul[i] = 0u;
        }
    }

    unsigned int prefix = 0, mask = 0;
    int k = Kq;
    for (int bit = 31; bit >= 0; --bit) {
        const unsigned int m2   = mask | (1u << bit);
        const unsigned int test = prefix | (1u << bit);
        int cnt = 0;
#pragma unroll
        for (int i = 0; i < NLOC; i++)
            cnt += ((ul[i] & m2) == test);
        cnt = __reduce_add_sync(0xffffffffu, cnt);
        if (cnt >= k) prefix = test; else k -= cnt;
        mask = m2;
    }
    const unsigned int th = prefix;
    const float thf = funmap(th);

    float sgt = 0.f, cgt = 0.f;
#pragma unroll
    for (int i = 0; i < NLOC; i++) {
        if (ul[i] > th) { sgt += lv[i]; cgt += 1.f; }
    }
    float sb = 0.f;
    for (int i = lane; i < Kq; i += 32) {
        int idx = g_idx_bkg[b * Kq + i];
        sb += col[idx];
    }
#pragma unroll
    for (int off = 16; off > 0; off >>= 1) {
        sgt += __shfl_xor_sync(0xffffffffu, sgt, off);
        cgt += __shfl_xor_sync(0xffffffffu, cgt, off);
        sb  += __shfl_xor_sync(0xffffffffu, sb,  off);
    }
    if (lane == 0) {
        g_sa[gw] = (sgt + ((float)Kq - cgt) * thf) / (float)Kq;
        g_sb[gw] = sb / (float)Kq;
    }
}

// ---------------------------------------------------------------------------
// K5: softmax over C for score_act / score_bkg (one warp per batch).
// ---------------------------------------------------------------------------
__global__ __launch_bounds__(32) void k_softmax_scores(float* __restrict__ out)
{
    const int b = blockIdx.x;
    const int lane = threadIdx.x;
    float va = (lane < Cq) ? g_sa[b * Cq + lane] : -INFINITY;
    float vb = (lane < Cq) ? g_sb[b * Cq + lane] : -INFINITY;
    float ma = va, mb = vb;
#pragma unroll
    for (int off = 16; off > 0; off >>= 1) {
        ma = fmaxf(ma, __shfl_xor_sync(0xffffffffu, ma, off));
        mb = fmaxf(mb, __shfl_xor_sync(0xffffffffu, mb, off));
    }
    float ea = (lane < Cq) ? expf(va - ma) : 0.f;
    float eb = (lane < Cq) ? expf(vb - mb) : 0.f;
    float sa = ea, sb = eb;
#pragma unroll
    for (int off = 16; off > 0; off >>= 1) {
        sa += __shfl_xor_sync(0xffffffffu, sa, off);
        sb += __shfl_xor_sync(0xffffffffu, sb, off);
    }
    if (lane < Cq) {
        out[OFF_SA + b * Cq + lane] = ea / sa;
        out[OFF_SB + b * Cq + lane] = eb / sb;
    }
}

// ---------------------------------------------------------------------------
extern "C" void kernel_launch(void* const* d_in, const int* in_sizes, int n_in,
                              void* d_out, int out_size)
{
    const float* x   = (const float*)d_in[0];   // (B,T,F)
    const float* W   = (const float*)d_in[1];   // (C,F)
    const float* mk  = (const float*)d_in[2];   // (B,T,F)
    const float* sel = (const float*)d_in[3];   // (B,T)
    float* out = (float*)d_out;

    static cudaStream_t s2 = nullptr;
    static cudaEvent_t evA = nullptr, evB = nullptr, evSel = nullptr, evJ2 = nullptr;
    if (s2 == nullptr) {
        cudaStreamCreateWithFlags(&s2, cudaStreamNonBlocking);
        cudaEventCreateWithFlags(&evA, cudaEventDisableTiming);
        cudaEventCreateWithFlags(&evB, cudaEventDisableTiming);
        cudaEventCreateWithFlags(&evSel, cudaEventDisableTiming);
        cudaEventCreateWithFlags(&evJ2, cudaEventDisableTiming);
    }

    const int smem_bytes = (RPB * CHUNK + 2 * Cq * CHUNK) * sizeof(float4);  // 56KB
    cudaFuncSetAttribute(k_main, cudaFuncAttributeMaxDynamicSharedMemorySize, smem_bytes);

    k_main<<<NROWS / RPB, 256, smem_bytes>>>((const float4*)x, (const float4*)mk,
                                             (const float4*)W, out);

    // fork: cas softmax/transpose on s2, selection on main
    cudaEventRecord(evA, (cudaStream_t)0);
    cudaStreamWaitEvent(s2, evA, 0);
    k_cas_softmax<<<NROWS / 8, 256, 0, s2>>>(out);
    cudaEventRecord(evB, s2);

    k_select<<<Bq, 256>>>(sel);
    cudaEventRecord(evSel, (cudaStream_t)0);

    // act gather on s2 (after select)
    cudaStreamWaitEvent(s2, evSel, 0);
    k_gather<<<Bq * Kq, 128, 0, s2>>>((const float4*)x, out, 0);
    cudaEventRecord(evJ2, s2);

    // scores path on main (needs casT + idx_bkg)
    cudaStreamWaitEvent((cudaStream_t)0, evB, 0);
    k_scores<<<(Bq * Cq + 7) / 8, 256>>>();
    k_softmax_scores<<<Bq, 32>>>(out);
    k_gather<<<Bq * Kq, 128>>>((const float4*)x, out, 1);

    cudaStreamWaitEvent((cudaStream_t)0, evJ2, 0);
}

// round 7
// speedup vs baseline: 2.1448x; 2.1448x over previous
#include <cuda_runtime.h>
#include <math.h>

// Problem constants
#define Bq 16
#define Tq 750
#define Fq 4096
#define Cq 20
#define Kq 93           // T / 8
#define F4 (Fq/4)       // 1024 float4 per row
#define NROWS (Bq*Tq)   // 12000

#define CHUNK 64        // float4 per F-chunk (16 chunks per row)
#define ROWS_PER_BLOCK 16
#define TPAD 768        // padded T for transposed cas

// Output layout (concatenated in reference return order, float32)
#define OFF_SA   0L
#define OFF_SB   320L
#define OFF_FA   640L
#define OFF_FB   (OFF_FA + (long)Bq*Kq*Fq)
#define OFF_FEAT (OFF_FB + (long)Bq*Kq*Fq)
#define OFF_CS   (OFF_FEAT + (long)NROWS*Fq)

// Scratch (static device globals; no runtime allocation)
__device__ float g_casT[Bq*Cq*TPAD];
__device__ float g_mag[NROWS];
__device__ int   g_idx_act[Bq*Kq];
__device__ int   g_idx_bkg[Bq*Kq];
__device__ float g_sa[Bq*Cq];
__device__ float g_sb[Bq*Cq];

// Monotone float <-> uint order map (total order)
__device__ __forceinline__ unsigned int fmap(float f)
{
    unsigned int u = __float_as_uint(f);
    return (u & 0x80000000u) ? ~u : (u | 0x80000000u);
}
__device__ __forceinline__ float funmap(unsigned int u)
{
    return (u & 0x80000000u) ? __uint_as_float(u ^ 0x80000000u)
                             : __uint_as_float(~u);
}

__device__ __forceinline__ void bar_named(int id)
{
    asm volatile("bar.sync %0, 128;" :: "r"(id) : "memory");
}

// 128-thread k-th largest using a named barrier (two instances run
// concurrently in one 256-thread block). 4-bit radix descent.
__device__ unsigned int kth_largest_h(const unsigned int* __restrict__ v, int n,
                                      int k, int* s_hist, int ltid, int barid)
{
    unsigned int prefix = 0;
    for (int shift = 28; shift >= 0; shift -= 4) {
        if (ltid < 16) s_hist[ltid] = 0;
        bar_named(barid);
        const unsigned int mask_hi = (shift == 28) ? 0u : (0xFFFFFFFFu << (shift + 4));
        for (int t = ltid; t < n; t += 128) {
            unsigned int x = v[t];
            if ((x & mask_hi) == prefix)
                atomicAdd(&s_hist[(x >> shift) & 15], 1);
        }
        bar_named(barid);
        int kk = k;
        int d = 15;
        for (; d > 0; d--) {
            int c = s_hist[d];
            if (kk <= c) break;
            kk -= c;
        }
        prefix |= (unsigned int)d << shift;
        k = kk;
        bar_named(barid);
    }
    return prefix;
}

// ---------------------------------------------------------------------------
// K1: fused stream kernel. Block = 256 threads = 8 warps = 16 rows (2/warp).
// F processed in 16 chunks of 64 float4; W slice (20x64 float4 = 20KB) is
// cp.async-prefetched into a ping-pong smem buffer one chunk ahead.
//   masked GEMM (20 classes), sumsq, features copy,
//   per-row softmax -> cas_softmax; raw cas (transposed) + mag -> scratch.
// ---------------------------------------------------------------------------
__global__ __launch_bounds__(256, 2) void k_main(const float4* __restrict__ x4,
                                                 const float4* __restrict__ m4,
                                                 const float4* __restrict__ w4,
                                                 float* __restrict__ out)
{
    __shared__ float4 wsh[2][Cq * CHUNK];   // 2 x 20 KB

    const int tid  = threadIdx.x;
    const int wid  = tid >> 5;
    const int lane = tid & 31;
    const int r0 = blockIdx.x * ROWS_PER_BLOCK + wid * 2;
    const int r1 = r0 + 1;

    const float4* __restrict__ xa = x4 + (long)r0 * F4;
    const float4* __restrict__ xb = x4 + (long)r1 * F4;
    const float4* __restrict__ ma = m4 + (long)r0 * F4;
    const float4* __restrict__ mb = m4 + (long)r1 * F4;
    float4* __restrict__ fa = reinterpret_cast<float4*>(out + OFF_FEAT) + (long)r0 * F4;
    float4* __restrict__ fb = reinterpret_cast<float4*>(out + OFF_FEAT) + (long)r1 * F4;

    float acc0[Cq], acc1[Cq];
#pragma unroll
    for (int c = 0; c < Cq; c++) { acc0[c] = 0.f; acc1[c] = 0.f; }
    float sq0 = 0.f, sq1 = 0.f;

    // stage chunk ch of W into buffer buf via cp.async (no regs, no wait)
    auto stage = [&](int ch, int buf) {
        const int jc = ch * CHUNK;
#pragma unroll
        for (int q = 0; q < (Cq * CHUNK) / 256; q++) {   // 5 per thread
            int idx = tid + 256 * q;
            const float4* src = &w4[(idx >> 6) * F4 + jc + (idx & (CHUNK - 1))];
            unsigned int dst = (unsigned int)__cvta_generic_to_shared(&wsh[buf][idx]);
            asm volatile("cp.async.cg.shared.global [%0], [%1], 16;"
                         :: "r"(dst), "l"(src));
        }
        asm volatile("cp.async.commit_group;");
    };

    stage(0, 0);

    for (int ch = 0; ch < F4 / CHUNK; ch++) {
        const int buf = ch & 1;
        asm volatile("cp.async.wait_group 0;");
        __syncthreads();            // all copies visible; prior reads of other buf done
        if (ch + 1 < F4 / CHUNK) stage(ch + 1, buf ^ 1);

        const int jc = ch * CHUNK;
#pragma unroll
        for (int ii = 0; ii < CHUNK / 32; ii++) {
            const int jj = lane + 32 * ii;
            const int j  = jc + jj;
            float4 a0 = xa[j];
            float4 a1 = xb[j];
            float4 q0 = ma[j];
            float4 q1 = mb[j];
            fa[j] = a0;
            fb[j] = a1;
            sq0 = fmaf(a0.x,a0.x, fmaf(a0.y,a0.y, fmaf(a0.z,a0.z, fmaf(a0.w,a0.w, sq0))));
            sq1 = fmaf(a1.x,a1.x, fmaf(a1.y,a1.y, fmaf(a1.z,a1.z, fmaf(a1.w,a1.w, sq1))));
            q0.x *= a0.x; q0.y *= a0.y; q0.z *= a0.z; q0.w *= a0.w;
            q1.x *= a1.x; q1.y *= a1.y; q1.z *= a1.z; q1.w *= a1.w;
#pragma unroll
            for (int c = 0; c < Cq; c++) {
                float4 w = wsh[buf][c * CHUNK + jj];
                acc0[c] = fmaf(q0.x,w.x, fmaf(q0.y,w.y, fmaf(q0.z,w.z, fmaf(q0.w,w.w, acc0[c]))));
                acc1[c] = fmaf(q1.x,w.x, fmaf(q1.y,w.y, fmaf(q1.z,w.z, fmaf(q1.w,w.w, acc1[c]))));
            }
        }
    }

    // warp tree reduction (butterfly)
#pragma unroll
    for (int off = 16; off > 0; off >>= 1) {
        sq0 += __shfl_xor_sync(0xffffffffu, sq0, off);
        sq1 += __shfl_xor_sync(0xffffffffu, sq1, off);
#pragma unroll
        for (int c = 0; c < Cq; c++) {
            acc0[c] += __shfl_xor_sync(0xffffffffu, acc0[c], off);
            acc1[c] += __shfl_xor_sync(0xffffffffu, acc1[c], off);
        }
    }

    float v0 = 0.f, v1 = 0.f;
#pragma unroll
    for (int c = 0; c < Cq; c++) {
        if (lane == c) { v0 = acc0[c]; v1 = acc1[c]; }
    }

    float mm0 = (lane < Cq) ? v0 : -INFINITY;
    float mm1 = (lane < Cq) ? v1 : -INFINITY;
#pragma unroll
    for (int off = 16; off > 0; off >>= 1) {
        mm0 = fmaxf(mm0, __shfl_xor_sync(0xffffffffu, mm0, off));
        mm1 = fmaxf(mm1, __shfl_xor_sync(0xffffffffu, mm1, off));
    }
    float e0 = (lane < Cq) ? expf(v0 - mm0) : 0.f;
    float e1 = (lane < Cq) ? expf(v1 - mm1) : 0.f;
    float s0 = e0, s1 = e1;
#pragma unroll
    for (int off = 16; off > 0; off >>= 1) {
        s0 += __shfl_xor_sync(0xffffffffu, s0, off);
        s1 += __shfl_xor_sync(0xffffffffu, s1, off);
    }
    if (lane < Cq) {
        out[OFF_CS + (long)r0 * Cq + lane] = e0 / s0;
        out[OFF_CS + (long)r1 * Cq + lane] = e1 / s1;
        const int b0 = r0 / Tq, t0 = r0 - b0 * Tq;
        const int b1 = r1 / Tq, t1 = r1 - b1 * Tq;
        g_casT[(b0 * Cq + lane) * TPAD + t0] = v0;
        g_casT[(b1 * Cq + lane) * TPAD + t1] = v1;
    }
    if (lane == 0) {
        g_mag[r0] = sqrtf(sq0);
        g_mag[r1] = sqrtf(sq1);
    }
}

// ---------------------------------------------------------------------------
// K2: per-batch selection. Halves of the block process the act and bkg lists
// concurrently (named barriers). Radix threshold + stable rank-count of the
// ~93 candidates (exact jax.lax.top_k order).
// ---------------------------------------------------------------------------
__global__ __launch_bounds__(256) void k_select(const float* __restrict__ sel)
{
    const int b = blockIdx.x;
    const int tid = threadIdx.x;
    __shared__ unsigned int ua[Tq];
    __shared__ unsigned int ub[Tq];
    __shared__ float red[256];
    __shared__ int s_histA[16];
    __shared__ int s_histB[16];

    float lmax = -INFINITY;
    for (int t = tid; t < Tq; t += 256) {
        float m = g_mag[b * Tq + t];
        ua[t] = __float_as_uint(m);
        lmax = fmaxf(lmax, m);
    }
    red[tid] = lmax;
    __syncthreads();
    for (int s = 128; s > 0; s >>= 1) {
        if (tid < s) red[tid] = fmaxf(red[tid], red[tid + s]);
        __syncthreads();
    }
    const float mx = red[0];
    __syncthreads();

    for (int t = tid; t < Tq; t += 256) {
        float m = __uint_as_float(ua[t]);
        float s = sel[b * Tq + t];
        float va = m * s + 0.0f;
        float vr = (mx - m) * s + 0.0f;
        ua[t] = fmap(va);
        ub[t] = fmap(vr);
    }
    __syncthreads();

    if (tid < 128) {
        const unsigned int thA = kth_largest_h(ua, Tq, Kq, s_histA, tid, 1);
        for (int t = tid; t < Tq; t += 128) {
            unsigned int xA = ua[t];
            if (xA >= thA) {
                int r = 0;
                for (int j = 0; j < Tq; j++) {
                    unsigned int u = ua[j];
                    r += (u > xA) || (u == xA && j < t);
                }
                if (r < Kq) g_idx_act[b * Kq + r] = t;
            }
        }
    } else {
        const int lt = tid - 128;
        const unsigned int thB = kth_largest_h(ub, Tq, Kq, s_histB, lt, 2);
        for (int t = lt; t < Tq; t += 128) {
            unsigned int xB = ub[t];
            if (xB >= thB) {
                int r = 0;
                for (int j = 0; j < Tq; j++) {
                    unsigned int u = ub[j];
                    r += (u > xB) || (u == xB && j < t);
                }
                if (r < Kq) g_idx_bkg[b * Kq + r] = t;
            }
        }
    }
}

// ---------------------------------------------------------------------------
// K3: gather feat_act / feat_bkg rows from x.
// ---------------------------------------------------------------------------
__global__ __launch_bounds__(128) void k_gather(const float4* __restrict__ x4,
                                                float* __restrict__ out)
{
    const int i = blockIdx.x;           // b*93 + k
    const int b = i / Kq;
    const int t = (blockIdx.y == 0) ? g_idx_act[i] : g_idx_bkg[i];
    const float4* __restrict__ src = x4 + ((long)(b * Tq + t)) * F4;
    float4* __restrict__ dst =
        reinterpret_cast<float4*>(out + (blockIdx.y == 0 ? OFF_FA : OFF_FB)) + (long)i * F4;
#pragma unroll
    for (int j = threadIdx.x; j < F4; j += 128) dst[j] = src[j];
}

// ---------------------------------------------------------------------------
// K4: warp per (b,c), coalesced loads from g_casT, no barriers.
// 1-bit radix descent with __reduce_add_sync finds the 93rd-largest; sum of
// top-93 = sum(v>th) + (93 - n_gt)*th (order-independent). Plus idx_bkg mean.
// ---------------------------------------------------------------------------
#define NLOC 24   // ceil(750/32)
__global__ __launch_bounds__(256) void k_scores()
{
    const int gw = (blockIdx.x * 256 + threadIdx.x) >> 5;   // 0..319
    const int lane = threadIdx.x & 31;
    if (gw >= Bq * Cq) return;
    const int b = gw / Cq;
    const float* __restrict__ col = &g_casT[gw * TPAD];

    float lv[NLOC];
    unsigned int ul[NLOC];
#pragma unroll
    for (int i = 0; i < NLOC; i++) {
        int t = lane + 32 * i;
        if (t < Tq) {
            float v = col[t];
            lv[i] = v;
            ul[i] = fmap(v);
        } else {
            lv[i] = 0.f;
            ul[i] = 0u;     // below every real mapped value
        }
    }

    // 1-bit radix descent, 32 passes, warp-collective
    unsigned int prefix = 0, mask = 0;
    int k = Kq;
    for (int bit = 31; bit >= 0; --bit) {
        const unsigned int m2   = mask | (1u << bit);
        const unsigned int test = prefix | (1u << bit);
        int cnt = 0;
#pragma unroll
        for (int i = 0; i < NLOC; i++)
            cnt += ((ul[i] & m2) == test);
        cnt = __reduce_add_sync(0xffffffffu, cnt);
        if (cnt >= k) prefix = test; else k -= cnt;
        mask = m2;
    }
    const unsigned int th = prefix;
    const float thf = funmap(th);

    float sgt = 0.f, cgt = 0.f;
#pragma unroll
    for (int i = 0; i < NLOC; i++) {
        if (ul[i] > th) { sgt += lv[i]; cgt += 1.f; }
    }
    float sb = 0.f;
    for (int i = lane; i < Kq; i += 32) {
        int idx = g_idx_bkg[b * Kq + i];
        sb += col[idx];
    }
#pragma unroll
    for (int off = 16; off > 0; off >>= 1) {
        sgt += __shfl_xor_sync(0xffffffffu, sgt, off);
        cgt += __shfl_xor_sync(0xffffffffu, cgt, off);
        sb  += __shfl_xor_sync(0xffffffffu, sb,  off);
    }
    if (lane == 0) {
        g_sa[gw] = (sgt + ((float)Kq - cgt) * thf) / (float)Kq;
        g_sb[gw] = sb / (float)Kq;
    }
}

// ---------------------------------------------------------------------------
// K5: softmax over C for score_act / score_bkg (one warp per batch).
// ---------------------------------------------------------------------------
__global__ __launch_bounds__(32) void k_softmax_scores(float* __restrict__ out)
{
    const int b = blockIdx.x;
    const int lane = threadIdx.x;
    float va = (lane < Cq) ? g_sa[b * Cq + lane] : -INFINITY;
    float vb = (lane < Cq) ? g_sb[b * Cq + lane] : -INFINITY;
    float ma = va, mb = vb;
#pragma unroll
    for (int off = 16; off > 0; off >>= 1) {
        ma = fmaxf(ma, __shfl_xor_sync(0xffffffffu, ma, off));
        mb = fmaxf(mb, __shfl_xor_sync(0xffffffffu, mb, off));
    }
    float ea = (lane < Cq) ? expf(va - ma) : 0.f;
    float eb = (lane < Cq) ? expf(vb - mb) : 0.f;
    float sa = ea, sb = eb;
#pragma unroll
    for (int off = 16; off > 0; off >>= 1) {
        sa += __shfl_xor_sync(0xffffffffu, sa, off);
        sb += __shfl_xor_sync(0xffffffffu, sb, off);
    }
    if (lane < Cq) {
        out[OFF_SA + b * Cq + lane] = ea / sa;
        out[OFF_SB + b * Cq + lane] = eb / sb;
    }
}

// ---------------------------------------------------------------------------
extern "C" void kernel_launch(void* const* d_in, const int* in_sizes, int n_in,
                              void* d_out, int out_size)
{
    const float* x   = (const float*)d_in[0];   // (B,T,F)
    const float* W   = (const float*)d_in[1];   // (C,F)
    const float* mk  = (const float*)d_in[2];   // (B,T,F)
    const float* sel = (const float*)d_in[3];   // (B,T)
    float* out = (float*)d_out;

    static cudaStream_t s2 = nullptr;
    static cudaEvent_t evFork = nullptr, evJoin = nullptr;
    if (s2 == nullptr) {
        cudaStreamCreateWithFlags(&s2, cudaStreamNonBlocking);
        cudaEventCreateWithFlags(&evFork, cudaEventDisableTiming);
        cudaEventCreateWithFlags(&evJoin, cudaEventDisableTiming);
    }

    k_main<<<NROWS / ROWS_PER_BLOCK, 256>>>((const float4*)x, (const float4*)mk,
                                            (const float4*)W, out);
    k_select<<<Bq, 256>>>(sel);

    // fork: gather runs concurrently with scores+softmax
    cudaEventRecord(evFork, (cudaStream_t)0);
    cudaStreamWaitEvent(s2, evFork, 0);
    {
        dim3 grid(Bq * Kq, 2);
        k_gather<<<grid, 128, 0, s2>>>((const float4*)x, out);
    }
    k_scores<<<(Bq * Cq + 7) / 8, 256>>>();
    k_softmax_scores<<<Bq, 32>>>(out);
    cudaEventRecord(evJoin, s2);
    cudaStreamWaitEvent((cudaStream_t)0, evJoin, 0);
}

// round 9
// speedup vs baseline: 2.1707x; 1.0121x over previous
#include <cuda_runtime.h>
#include <math.h>

// Problem constants
#define Bq 16
#define Tq 750
#define Fq 4096
#define Cq 20
#define Kq 93           // T / 8
#define F4 (Fq/4)       // 1024 float4 per row
#define NROWS (Bq*Tq)   // 12000

#define CHUNK 64        // float4 per F-chunk (16 chunks per row)
#define NCH (F4/CHUNK)
#define RPB 16          // rows per block
#define TPAD 768        // padded T for transposed cas

// Output layout (concatenated in reference return order, float32)
#define OFF_SA   0L
#define OFF_SB   320L
#define OFF_FA   640L
#define OFF_FB   (OFF_FA + (long)Bq*Kq*Fq)
#define OFF_FEAT (OFF_FB + (long)Bq*Kq*Fq)
#define OFF_CS   (OFF_FEAT + (long)NROWS*Fq)

// Scratch (static device globals; no runtime allocation)
__device__ float g_casT[Bq*Cq*TPAD];
__device__ float g_mag[NROWS];
__device__ int   g_idx_act[Bq*Kq];
__device__ int   g_idx_bkg[Bq*Kq];
__device__ float g_sa[Bq*Cq];
__device__ float g_sb[Bq*Cq];

// Monotone float <-> uint order map (total order)
__device__ __forceinline__ unsigned int fmap(float f)
{
    unsigned int u = __float_as_uint(f);
    return (u & 0x80000000u) ? ~u : (u | 0x80000000u);
}
__device__ __forceinline__ float funmap(unsigned int u)
{
    return (u & 0x80000000u) ? __uint_as_float(u ^ 0x80000000u)
                             : __uint_as_float(~u);
}

__device__ __forceinline__ void bar_named(int id)
{
    asm volatile("bar.sync %0, 128;" :: "r"(id) : "memory");
}

// 128-thread k-th largest using a named barrier (two instances run
// concurrently in one 256-thread block). 4-bit radix descent.
__device__ unsigned int kth_largest_h(const unsigned int* __restrict__ v, int n,
                                      int k, int* s_hist, int ltid, int barid)
{
    unsigned int prefix = 0;
    for (int shift = 28; shift >= 0; shift -= 4) {
        if (ltid < 16) s_hist[ltid] = 0;
        bar_named(barid);
        const unsigned int mask_hi = (shift == 28) ? 0u : (0xFFFFFFFFu << (shift + 4));
        for (int t = ltid; t < n; t += 128) {
            unsigned int x = v[t];
            if ((x & mask_hi) == prefix)
                atomicAdd(&s_hist[(x >> shift) & 15], 1);
        }
        bar_named(barid);
        int kk = k;
        int d = 15;
        for (; d > 0; d--) {
            int c = s_hist[d];
            if (kk <= c) break;
            kk -= c;
        }
        prefix |= (unsigned int)d << shift;
        k = kk;
        bar_named(barid);
    }
    return prefix;
}

// ---------------------------------------------------------------------------
// K1: fused stream kernel. Block = 256 threads = 8 warps = 16 rows (2/warp).
// ALL inputs (x, mask, W) for each 64-float4 chunk are cp.async-staged into a
// double-buffered smem pipeline, so the compute loop has no global-load
// scoreboard waits: DRAM is paced by the async pipeline, FMA/LDS overlap it.
// Dynamic smem: 2 x (16KB x + 16KB m + 20KB W) = 104 KB -> 2 blocks/SM.
// ---------------------------------------------------------------------------
extern __shared__ float4 sm_dyn[];

__global__ __launch_bounds__(256, 2) void k_main(const float4* __restrict__ x4,
                                                 const float4* __restrict__ m4,
                                                 const float4* __restrict__ w4,
                                                 float* __restrict__ out)
{
    float4* xsh = sm_dyn;                 // [2][RPB*CHUNK]  (2 x 1024)
    float4* msh = sm_dyn + 2048;          // [2][RPB*CHUNK]
    float4* wsh = sm_dyn + 4096;          // [2][Cq*CHUNK]   (2 x 1280)

    const int tid  = threadIdx.x;
    const int wid  = tid >> 5;
    const int lane = tid & 31;
    const int rbase = blockIdx.x * RPB;
    const int r0 = rbase + wid * 2;
    const int r1 = r0 + 1;

    float4* __restrict__ fa = reinterpret_cast<float4*>(out + OFF_FEAT) + (long)r0 * F4;
    float4* __restrict__ fb = reinterpret_cast<float4*>(out + OFF_FEAT) + (long)r1 * F4;

    float acc0[Cq], acc1[Cq];
#pragma unroll
    for (int c = 0; c < Cq; c++) { acc0[c] = 0.f; acc1[c] = 0.f; }
    float sq0 = 0.f, sq1 = 0.f;

    // stage chunk ch (x, mask, W) into buffer buf; one commit group
    auto stage = [&](int ch, int buf) {
        const int jc = ch * CHUNK;
        // x and mask: 1024 float4 each -> 4 per thread
#pragma unroll
        for (int q = 0; q < (RPB * CHUNK) / 256; q++) {
            int idx = tid + 256 * q;                  // row = idx>>6, col = idx&63
            const float4* sx = x4 + (long)(rbase + (idx >> 6)) * F4 + jc + (idx & (CHUNK - 1));
            const float4* sm_ = m4 + (long)(rbase + (idx >> 6)) * F4 + jc + (idx & (CHUNK - 1));
            unsigned int dx = (unsigned int)__cvta_generic_to_shared(&xsh[buf * 1024 + idx]);
            unsigned int dm = (unsigned int)__cvta_generic_to_shared(&msh[buf * 1024 + idx]);
            asm volatile("cp.async.cg.shared.global [%0], [%1], 16;" :: "r"(dx), "l"(sx));
            asm volatile("cp.async.cg.shared.global [%0], [%1], 16;" :: "r"(dm), "l"(sm_));
        }
        // W: 1280 float4 -> 5 per thread
#pragma unroll
        for (int q = 0; q < (Cq * CHUNK) / 256; q++) {
            int idx = tid + 256 * q;
            const float4* src = &w4[(idx >> 6) * F4 + jc + (idx & (CHUNK - 1))];
            unsigned int dst = (unsigned int)__cvta_generic_to_shared(&wsh[buf * (Cq * CHUNK) + idx]);
            asm volatile("cp.async.cg.shared.global [%0], [%1], 16;" :: "r"(dst), "l"(src));
        }
        asm volatile("cp.async.commit_group;");
    };

    stage(0, 0);

    for (int ch = 0; ch < NCH; ch++) {
        const int buf = ch & 1;
        asm volatile("cp.async.wait_group 0;");
        __syncthreads();            // chunk ch staged; prior reads of other buf done
        if (ch + 1 < NCH) stage(ch + 1, buf ^ 1);

        const float4* xb = &xsh[buf * 1024];
        const float4* mb = &msh[buf * 1024];
        const float4* wb = &wsh[buf * (Cq * CHUNK)];
        const int jc = ch * CHUNK;
        const int rp0 = (wid * 2) * CHUNK;
        const int rp1 = (wid * 2 + 1) * CHUNK;
#pragma unroll
        for (int ii = 0; ii < CHUNK / 32; ii++) {
            const int jj = lane + 32 * ii;
            const int j  = jc + jj;
            float4 a0 = xb[rp0 + jj];
            float4 a1 = xb[rp1 + jj];
            float4 q0 = mb[rp0 + jj];
            float4 q1 = mb[rp1 + jj];
            fa[j] = a0;
            fb[j] = a1;
            sq0 = fmaf(a0.x,a0.x, fmaf(a0.y,a0.y, fmaf(a0.z,a0.z, fmaf(a0.w,a0.w, sq0))));
            sq1 = fmaf(a1.x,a1.x, fmaf(a1.y,a1.y, fmaf(a1.z,a1.z, fmaf(a1.w,a1.w, sq1))));
            q0.x *= a0.x; q0.y *= a0.y; q0.z *= a0.z; q0.w *= a0.w;
            q1.x *= a1.x; q1.y *= a1.y; q1.z *= a1.z; q1.w *= a1.w;
#pragma unroll
            for (int c = 0; c < Cq; c++) {
                float4 w = wb[c * CHUNK + jj];
                acc0[c] = fmaf(q0.x,w.x, fmaf(q0.y,w.y, fmaf(q0.z,w.z, fmaf(q0.w,w.w, acc0[c]))));
                acc1[c] = fmaf(q1.x,w.x, fmaf(q1.y,w.y, fmaf(q1.z,w.z, fmaf(q1.w,w.w, acc1[c]))));
            }
        }
    }

    // warp tree reduction (butterfly)
#pragma unroll
    for (int off = 16; off > 0; off >>= 1) {
        sq0 += __shfl_xor_sync(0xffffffffu, sq0, off);
        sq1 += __shfl_xor_sync(0xffffffffu, sq1, off);
#pragma unroll
        for (int c = 0; c < Cq; c++) {
            acc0[c] += __shfl_xor_sync(0xffffffffu, acc0[c], off);
            acc1[c] += __shfl_xor_sync(0xffffffffu, acc1[c], off);
        }
    }

    float v0 = 0.f, v1 = 0.f;
#pragma unroll
    for (int c = 0; c < Cq; c++) {
        if (lane == c) { v0 = acc0[c]; v1 = acc1[c]; }
    }

    float mm0 = (lane < Cq) ? v0 : -INFINITY;
    float mm1 = (lane < Cq) ? v1 : -INFINITY;
#pragma unroll
    for (int off = 16; off > 0; off >>= 1) {
        mm0 = fmaxf(mm0, __shfl_xor_sync(0xffffffffu, mm0, off));
        mm1 = fmaxf(mm1, __shfl_xor_sync(0xffffffffu, mm1, off));
    }
    float e0 = (lane < Cq) ? expf(v0 - mm0) : 0.f;
    float e1 = (lane < Cq) ? expf(v1 - mm1) : 0.f;
    float s0 = e0, s1 = e1;
#pragma unroll
    for (int off = 16; off > 0; off >>= 1) {
        s0 += __shfl_xor_sync(0xffffffffu, s0, off);
        s1 += __shfl_xor_sync(0xffffffffu, s1, off);
    }
    if (lane < Cq) {
        out[OFF_CS + (long)r0 * Cq + lane] = e0 / s0;
        out[OFF_CS + (long)r1 * Cq + lane] = e1 / s1;
        const int b0 = r0 / Tq, t0 = r0 - b0 * Tq;
        const int b1 = r1 / Tq, t1 = r1 - b1 * Tq;
        g_casT[(b0 * Cq + lane) * TPAD + t0] = v0;
        g_casT[(b1 * Cq + lane) * TPAD + t1] = v1;
    }
    if (lane == 0) {
        g_mag[r0] = sqrtf(sq0);
        g_mag[r1] = sqrtf(sq1);
    }
}

// ---------------------------------------------------------------------------
// K2: per-batch selection. Halves of the block process the act and bkg lists
// concurrently (named barriers). Radix threshold + stable rank-count of the
// ~93 candidates (exact jax.lax.top_k order).
// ---------------------------------------------------------------------------
__global__ __launch_bounds__(256) void k_select(const float* __restrict__ sel)
{
    const int b = blockIdx.x;
    const int tid = threadIdx.x;
    __shared__ unsigned int ua[Tq];
    __shared__ unsigned int ub[Tq];
    __shared__ float red[256];
    __shared__ int s_histA[16];
    __shared__ int s_histB[16];

    float lmax = -INFINITY;
    for (int t = tid; t < Tq; t += 256) {
        float m = g_mag[b * Tq + t];
        ua[t] = __float_as_uint(m);
        lmax = fmaxf(lmax, m);
    }
    red[tid] = lmax;
    __syncthreads();
    for (int s = 128; s > 0; s >>= 1) {
        if (tid < s) red[tid] = fmaxf(red[tid], red[tid + s]);
        __syncthreads();
    }
    const float mx = red[0];
    __syncthreads();

    for (int t = tid; t < Tq; t += 256) {
        float m = __uint_as_float(ua[t]);
        float s = sel[b * Tq + t];
        float va = m * s + 0.0f;
        float vr = (mx - m) * s + 0.0f;
        ua[t] = fmap(va);
        ub[t] = fmap(vr);
    }
    __syncthreads();

    if (tid < 128) {
        const unsigned int thA = kth_largest_h(ua, Tq, Kq, s_histA, tid, 1);
        for (int t = tid; t < Tq; t += 128) {
            unsigned int xA = ua[t];
            if (xA >= thA) {
                int r = 0;
                for (int j = 0; j < Tq; j++) {
                    unsigned int u = ua[j];
                    r += (u > xA) || (u == xA && j < t);
                }
                if (r < Kq) g_idx_act[b * Kq + r] = t;
            }
        }
    } else {
        const int lt = tid - 128;
        const unsigned int thB = kth_largest_h(ub, Tq, Kq, s_histB, lt, 2);
        for (int t = lt; t < Tq; t += 128) {
            unsigned int xB = ub[t];
            if (xB >= thB) {
                int r = 0;
                for (int j = 0; j < Tq; j++) {
                    unsigned int u = ub[j];
                    r += (u > xB) || (u == xB && j < t);
                }
                if (r < Kq) g_idx_bkg[b * Kq + r] = t;
            }
        }
    }
}

// ---------------------------------------------------------------------------
// K3: gather feat_act / feat_bkg rows from x.
// ---------------------------------------------------------------------------
__global__ __launch_bounds__(128) void k_gather(const float4* __restrict__ x4,
                                                float* __restrict__ out)
{
    const int i = blockIdx.x;           // b*93 + k
    const int b = i / Kq;
    const int t = (blockIdx.y == 0) ? g_idx_act[i] : g_idx_bkg[i];
    const float4* __restrict__ src = x4 + ((long)(b * Tq + t)) * F4;
    float4* __restrict__ dst =
        reinterpret_cast<float4*>(out + (blockIdx.y == 0 ? OFF_FA : OFF_FB)) + (long)i * F4;
#pragma unroll
    for (int j = threadIdx.x; j < F4; j += 128) dst[j] = src[j];
}

// ---------------------------------------------------------------------------
// K4: warp per (b,c), coalesced loads from g_casT, no barriers.
// 1-bit radix descent with __reduce_add_sync finds the 93rd-largest; sum of
// top-93 = sum(v>th) + (93 - n_gt)*th (order-independent). Plus idx_bkg mean.
// ---------------------------------------------------------------------------
#define NLOC 24   // ceil(750/32)
__global__ __launch_bounds__(256) void k_scores()
{
    const int gw = (blockIdx.x * 256 + threadIdx.x) >> 5;   // 0..319
    const int lane = threadIdx.x & 31;
    if (gw >= Bq * Cq) return;
    const int b = gw / Cq;
    const float* __restrict__ col = &g_casT[gw * TPAD];

    float lv[NLOC];
    unsigned int ul[NLOC];
#pragma unroll
    for (int i = 0; i < NLOC; i++) {
        int t = lane + 32 * i;
        if (t < Tq) {
            float v = col[t];
            lv[i] = v;
            ul[i] = fmap(v);
        } else {
            lv[i] = 0.f;
            ul[i] = 0u;     // below every real mapped value
        }
    }

    // 1-bit radix descent, 32 passes, warp-collective
    unsigned int prefix = 0, mask = 0;
    int k = Kq;
    for (int bit = 31; bit >= 0; --bit) {
        const unsigned int m2   = mask | (1u << bit);
        const unsigned int test = prefix | (1u << bit);
        int cnt = 0;
#pragma unroll
        for (int i = 0; i < NLOC; i++)
            cnt += ((ul[i] & m2) == test);
        cnt = __reduce_add_sync(0xffffffffu, cnt);
        if (cnt >= k) prefix = test; else k -= cnt;
        mask = m2;
    }
    const unsigned int th = prefix;
    const float thf = funmap(th);

    float sgt = 0.f, cgt = 0.f;
#pragma unroll
    for (int i = 0; i < NLOC; i++) {
        if (ul[i] > th) { sgt += lv[i]; cgt += 1.f; }
    }
    float sb = 0.f;
    for (int i = lane; i < Kq; i += 32) {
        int idx = g_idx_bkg[b * Kq + i];
        sb += col[idx];
    }
#pragma unroll
    for (int off = 16; off > 0; off >>= 1) {
        sgt += __shfl_xor_sync(0xffffffffu, sgt, off);
        cgt += __shfl_xor_sync(0xffffffffu, cgt, off);
        sb  += __shfl_xor_sync(0xffffffffu, sb,  off);
    }
    if (lane == 0) {
        g_sa[gw] = (sgt + ((float)Kq - cgt) * thf) / (float)Kq;
        g_sb[gw] = sb / (float)Kq;
    }
}

// ---------------------------------------------------------------------------
// K5: softmax over C for score_act / score_bkg (one warp per batch).
// ---------------------------------------------------------------------------
__global__ __launch_bounds__(32) void k_softmax_scores(float* __restrict__ out)
{
    const int b = blockIdx.x;
    const int lane = threadIdx.x;
    float va = (lane < Cq) ? g_sa[b * Cq + lane] : -INFINITY;
    float vb = (lane < Cq) ? g_sb[b * Cq + lane] : -INFINITY;
    float ma = va, mb = vb;
#pragma unroll
    for (int off = 16; off > 0; off >>= 1) {
        ma = fmaxf(ma, __shfl_xor_sync(0xffffffffu, ma, off));
        mb = fmaxf(mb, __shfl_xor_sync(0xffffffffu, mb, off));
    }
    float ea = (lane < Cq) ? expf(va - ma) : 0.f;
    float eb = (lane < Cq) ? expf(vb - mb) : 0.f;
    float sa = ea, sb = eb;
#pragma unroll
    for (int off = 16; off > 0; off >>= 1) {
        sa += __shfl_xor_sync(0xffffffffu, sa, off);
        sb += __shfl_xor_sync(0xffffffffu, sb, off);
    }
    if (lane < Cq) {
        out[OFF_SA + b * Cq + lane] = ea / sa;
        out[OFF_SB + b * Cq + lane] = eb / sb;
    }
}

// ---------------------------------------------------------------------------
extern "C" void kernel_launch(void* const* d_in, const int* in_sizes, int n_in,
                              void* d_out, int out_size)
{
    const float* x   = (const float*)d_in[0];   // (B,T,F)
    const float* W   = (const float*)d_in[1];   // (C,F)
    const float* mk  = (const float*)d_in[2];   // (B,T,F)
    const float* sel = (const float*)d_in[3];   // (B,T)
    float* out = (float*)d_out;

    static cudaStream_t s2 = nullptr;
    static cudaEvent_t evFork = nullptr, evJoin = nullptr;
    if (s2 == nullptr) {
        cudaStreamCreateWithFlags(&s2, cudaStreamNonBlocking);
        cudaEventCreateWithFlags(&evFork, cudaEventDisableTiming);
        cudaEventCreateWithFlags(&evJoin, cudaEventDisableTiming);
    }

    const int smem_bytes = (2 * RPB * CHUNK * 2 + 2 * Cq * CHUNK) * sizeof(float4); // 104KB
    static bool attr_set = false;
    if (!attr_set) {
        cudaFuncSetAttribute(k_main, cudaFuncAttributeMaxDynamicSharedMemorySize, smem_bytes);
        attr_set = true;
    }

    k_main<<<NROWS / RPB, 256, smem_bytes>>>((const float4*)x, (const float4*)mk,
                                             (const float4*)W, out);
    k_select<<<Bq, 256>>>(sel);

    // fork: gather runs concurrently with scores+softmax
    cudaEventRecord(evFork, (cudaStream_t)0);
    cudaStreamWaitEvent(s2, evFork, 0);
    {
        dim3 grid(Bq * Kq, 2);
        k_gather<<<grid, 128, 0, s2>>>((const float4*)x, out);
    }
    k_scores<<<(Bq * Cq + 7) / 8, 256>>>();
    k_softmax_scores<<<Bq, 32>>>(out);
    cudaEventRecord(evJoin, s2);
    cudaStreamWaitEvent((cudaStream_t)0, evJoin, 0);
}